// round 5
// baseline (speedup 1.0000x reference)
#include <cuda_runtime.h>
#include <math.h>

#define TT 2048
#define DD 1024
#define KQ 32
#define NT 8192
#define KTOP 4

typedef unsigned long long ull;

// scratch
__device__ float g_P[4][NT * 64];           // proj partials (k-split 4), cols 0..31=Q, 32..63=K
__device__ float g_Qf[NT * KQ];             // reduced Q [row][k]
__device__ float g_KT[4 * KQ * TT];         // reduced K transposed [b][k][t]
__device__ float g_cv[NT * 8];              // candidate values [row][half][4]
__device__ __align__(16) int g_ci[NT * 8];  // candidate indices

// ---- packed f32x2 helpers ---------------------------------------------------
__device__ __forceinline__ void unpack2(ull v, float& lo, float& hi) {
    asm("mov.b64 {%0, %1}, %2;" : "=f"(lo), "=f"(hi) : "l"(v));
}
__device__ __forceinline__ ull ffma2(ull a, ull b, ull c) {
    ull d;
    asm("fma.rn.f32x2 %0, %1, %2, %3;" : "=l"(d) : "l"(a), "l"(b), "l"(c));
    return d;
}

// sorted top-4 insert (v0>=v1>=v2>=v3)
__device__ __forceinline__ void upd4(float* v, int* ix, float s, int si) {
    if (s > v[3]) {
        if (s > v[1]) {
            v[3] = v[2]; ix[3] = ix[2]; v[2] = v[1]; ix[2] = ix[1];
            if (s > v[0]) { v[1] = v[0]; ix[1] = ix[0]; v[0] = s; ix[0] = si; }
            else          { v[1] = s; ix[1] = si; }
        } else {
            if (s > v[2]) { v[3] = v[2]; ix[3] = ix[2]; v[2] = s; ix[2] = si; }
            else          { v[3] = s; ix[3] = si; }
        }
    }
}

// ---------------------------------------------------------------------------
// Kernel 1: projection partials. grid = 512 (128 row-tiles x 4 k-split), 256 thr.
// ---------------------------------------------------------------------------
__global__ __launch_bounds__(256) void proj_kernel(
    const float* __restrict__ x, const float* __restrict__ Wq,
    const float* __restrict__ Wk)
{
    __shared__ __align__(16) float Xd[32][132];  // [k][2*row] duplicated pairs
    __shared__ __align__(16) float Wt[32][68];   // [k][col]

    const int tid  = threadIdx.x;
    const int row0 = (blockIdx.x >> 2) * 64;
    const int kh   = blockIdx.x & 3;
    const int rg   = tid >> 4;      // 0..15
    const int tc   = tid & 15;      // 0..15
    const int r0   = rg * 4;

    ull acc[4][2];
    #pragma unroll
    for (int i = 0; i < 4; i++) { acc[i][0] = 0ULL; acc[i][1] = 0ULL; }

    for (int kt = 0; kt < 8; kt++) {
        const int kb = kh * 256 + kt * 32;
        #pragma unroll
        for (int l = 0; l < 2; l++) {
            int f = tid + l * 256;
            int row = f >> 3, kc = f & 7;
            float4 v = *(const float4*)&x[(size_t)(row0 + row) * DD + kb + kc * 4];
            *(float2*)&Xd[kc * 4 + 0][2 * row] = make_float2(v.x, v.x);
            *(float2*)&Xd[kc * 4 + 1][2 * row] = make_float2(v.y, v.y);
            *(float2*)&Xd[kc * 4 + 2][2 * row] = make_float2(v.z, v.z);
            *(float2*)&Xd[kc * 4 + 3][2 * row] = make_float2(v.w, v.w);
        }
        #pragma unroll
        for (int l = 0; l < 2; l++) {
            int f = tid + l * 256;
            int col = f >> 3, kc = f & 7;
            const float* Wr = (col < KQ) ? &Wq[col * DD] : &Wk[(col - KQ) * DD];
            float4 w = *(const float4*)&Wr[kb + kc * 4];
            Wt[kc * 4 + 0][col] = w.x;
            Wt[kc * 4 + 1][col] = w.y;
            Wt[kc * 4 + 2][col] = w.z;
            Wt[kc * 4 + 3][col] = w.w;
        }
        __syncthreads();

        #pragma unroll
        for (int k = 0; k < 32; k++) {
            ulonglong2 xa = *(const ulonglong2*)&Xd[k][2 * r0];
            ulonglong2 xb = *(const ulonglong2*)&Xd[k][2 * r0 + 4];
            ull w0 = *(const ull*)&Wt[k][2 * tc];
            ull w1 = *(const ull*)&Wt[k][2 * tc + 32];
            ull xr[4] = { xa.x, xa.y, xb.x, xb.y };
            #pragma unroll
            for (int i = 0; i < 4; i++) {
                acc[i][0] = ffma2(xr[i], w0, acc[i][0]);
                acc[i][1] = ffma2(xr[i], w1, acc[i][1]);
            }
        }
        __syncthreads();
    }

    #pragma unroll
    for (int i = 0; i < 4; i++) {
        size_t r = (size_t)(row0 + r0 + i) * 64;
        float lo, hi;
        unpack2(acc[i][0], lo, hi);
        *(float2*)&g_P[kh][r + 2 * tc] = make_float2(lo, hi);
        unpack2(acc[i][1], lo, hi);
        *(float2*)&g_P[kh][r + 2 * tc + 32] = make_float2(lo, hi);
    }
}

// ---------------------------------------------------------------------------
// Kernel 2: reduce partials + bias; write Q [row][k] and K transposed [b][k][t].
// ---------------------------------------------------------------------------
__global__ __launch_bounds__(256) void reduce_kernel(
    const float* __restrict__ bq, const float* __restrict__ bk)
{
    __shared__ __align__(16) float Ks[64][36];

    const int tid  = threadIdx.x;
    const int row0 = blockIdx.x * 64;
    const int b    = row0 >> 11;
    const int t0   = row0 & (TT - 1);

    #pragma unroll
    for (int l = 0; l < 4; l++) {
        int f = tid + l * 256;
        int row = f >> 4, c4 = f & 15;
        size_t base = (size_t)(row0 + row) * 64 + c4 * 4;
        float4 a = *(const float4*)&g_P[0][base];
        float4 p1 = *(const float4*)&g_P[1][base];
        float4 p2 = *(const float4*)&g_P[2][base];
        float4 p3 = *(const float4*)&g_P[3][base];
        float4 s;
        s.x = ((a.x + p1.x) + p2.x) + p3.x;
        s.y = ((a.y + p1.y) + p2.y) + p3.y;
        s.z = ((a.z + p1.z) + p2.z) + p3.z;
        s.w = ((a.w + p1.w) + p2.w) + p3.w;
        if (c4 < 8) {
            int c = c4 * 4;
            s.x += bq[c]; s.y += bq[c + 1]; s.z += bq[c + 2]; s.w += bq[c + 3];
            *(float4*)&g_Qf[(size_t)(row0 + row) * KQ + c] = s;
        } else {
            int c = c4 * 4 - 32;
            s.x += bk[c]; s.y += bk[c + 1]; s.z += bk[c + 2]; s.w += bk[c + 3];
            *(float4*)&Ks[row][c] = s;
        }
    }
    __syncthreads();

    #pragma unroll
    for (int l = 0; l < 2; l++) {
        int f = tid + l * 256;
        int k = f >> 4, c4 = f & 15;
        float4 o = { Ks[c4 * 4 + 0][k], Ks[c4 * 4 + 1][k],
                     Ks[c4 * 4 + 2][k], Ks[c4 * 4 + 3][k] };
        *(float4*)&g_KT[((size_t)b * KQ + k) * TT + t0 + c4 * 4] = o;
    }
}

// ---------------------------------------------------------------------------
// Kernel 3: similarity + top-4 candidates. grid = 512 (256 row-tiles x 2 halves).
// ---------------------------------------------------------------------------
__global__ __launch_bounds__(256) void sim_kernel()
{
    __shared__ __align__(16) float Qd[32][68];    // [k][2*row] duplicated
    __shared__ __align__(16) float Kt[32][132];   // [k][key]

    const int tid   = threadIdx.x;
    const int row0  = (blockIdx.x >> 1) * 32;
    const int khalf = blockIdx.x & 1;
    const int b     = row0 >> 11;
    const int rg    = tid >> 5;     // warp id: rows r0..r0+3
    const int cg    = tid & 31;     // lane: key pairs cg, cg+32
    const int r0    = rg * 4;

    {
        int row = tid >> 3, kc = tid & 7;
        float4 v = *(const float4*)&g_Qf[(size_t)(row0 + row) * KQ + kc * 4];
        *(float2*)&Qd[kc * 4 + 0][2 * row] = make_float2(v.x, v.x);
        *(float2*)&Qd[kc * 4 + 1][2 * row] = make_float2(v.y, v.y);
        *(float2*)&Qd[kc * 4 + 2][2 * row] = make_float2(v.z, v.z);
        *(float2*)&Qd[kc * 4 + 3][2 * row] = make_float2(v.w, v.w);
    }

    float tv[4][4]; int ti[4][4];
    #pragma unroll
    for (int i = 0; i < 4; i++)
        #pragma unroll
        for (int p = 0; p < 4; p++) { tv[i][p] = -INFINITY; ti[i][p] = 0; }

    __syncthreads();

    const float* KTb = &g_KT[(size_t)b * KQ * TT + khalf * 1024];

    for (int t = 0; t < 8; t++) {
        const int kbase = t * 128;
        #pragma unroll
        for (int l = 0; l < 4; l++) {
            int f = tid + l * 256;
            int k = f >> 5, c4 = f & 31;
            float4 v = *(const float4*)&KTb[(size_t)k * TT + kbase + c4 * 4];
            *(float4*)&Kt[k][c4 * 4] = v;
        }
        __syncthreads();

        ull acc[4][2];
        #pragma unroll
        for (int i = 0; i < 4; i++) { acc[i][0] = 0ULL; acc[i][1] = 0ULL; }

        #pragma unroll
        for (int k = 0; k < 32; k++) {
            ulonglong2 qa = *(const ulonglong2*)&Qd[k][2 * r0];
            ulonglong2 qb = *(const ulonglong2*)&Qd[k][2 * r0 + 4];
            ull k0 = *(const ull*)&Kt[k][2 * cg];
            ull k1 = *(const ull*)&Kt[k][2 * cg + 64];
            ull qr[4] = { qa.x, qa.y, qb.x, qb.y };
            #pragma unroll
            for (int i = 0; i < 4; i++) {
                acc[i][0] = ffma2(qr[i], k0, acc[i][0]);
                acc[i][1] = ffma2(qr[i], k1, acc[i][1]);
            }
        }

        const int i0 = khalf * 1024 + kbase + 2 * cg;
        #pragma unroll
        for (int i = 0; i < 4; i++) {
            float lo, hi;
            unpack2(acc[i][0], lo, hi);
            upd4(tv[i], ti[i], lo, i0);
            upd4(tv[i], ti[i], hi, i0 + 1);
            unpack2(acc[i][1], lo, hi);
            upd4(tv[i], ti[i], lo, i0 + 64);
            upd4(tv[i], ti[i], hi, i0 + 65);
        }
        __syncthreads();
    }

    // warp butterfly merge with SNAPSHOT: shuffle partner's full list first,
    // then insert. (Reading partner state mid-merge was the R4 bug.)
    #pragma unroll
    for (int off = 16; off; off >>= 1) {
        #pragma unroll
        for (int i = 0; i < 4; i++) {
            float ov[4]; int oi[4];
            #pragma unroll
            for (int p = 0; p < 4; p++) {
                ov[p] = __shfl_xor_sync(0xFFFFFFFFu, tv[i][p], off);
                oi[p] = __shfl_xor_sync(0xFFFFFFFFu, ti[i][p], off);
            }
            #pragma unroll
            for (int p = 0; p < 4; p++)
                upd4(tv[i], ti[i], ov[p], oi[p]);
        }
    }

    if (cg == 0) {
        #pragma unroll
        for (int i = 0; i < 4; i++) {
            size_t base = (size_t)(row0 + r0 + i) * 8 + khalf * 4;
            *(float4*)&g_cv[base] = make_float4(tv[i][0], tv[i][1], tv[i][2], tv[i][3]);
            *(int4*)&g_ci[base]   = make_int4(ti[i][0], ti[i][1], ti[i][2], ti[i][3]);
        }
    }
}

// ---------------------------------------------------------------------------
// Kernel 4: merge 8 candidates + gather + mean. Warp per row, grid = 1024.
// ---------------------------------------------------------------------------
__global__ __launch_bounds__(256) void gather_kernel(
    const float* __restrict__ x, float* __restrict__ out)
{
    const int tid  = threadIdx.x;
    const int wid  = tid >> 5;
    const int lane = tid & 31;
    const int row  = blockIdx.x * 8 + wid;
    const int b    = row >> 11;

    float cv[8]; int ci[8];
    {
        float4 a = *(const float4*)&g_cv[(size_t)row * 8];
        float4 c2 = *(const float4*)&g_cv[(size_t)row * 8 + 4];
        int4 ia = *(const int4*)&g_ci[(size_t)row * 8];
        int4 ib = *(const int4*)&g_ci[(size_t)row * 8 + 4];
        cv[0] = a.x; cv[1] = a.y; cv[2] = a.z; cv[3] = a.w;
        cv[4] = c2.x; cv[5] = c2.y; cv[6] = c2.z; cv[7] = c2.w;
        ci[0] = ia.x; ci[1] = ia.y; ci[2] = ia.z; ci[3] = ia.w;
        ci[4] = ib.x; ci[5] = ib.y; ci[6] = ib.z; ci[7] = ib.w;
    }
    int sel[4];
    #pragma unroll
    for (int p = 0; p < KTOP; p++) {
        int best = 0;
        #pragma unroll
        for (int k = 1; k < 8; k++)
            if (cv[k] > cv[best]) best = k;
        sel[p] = ci[best];
        cv[best] = -INFINITY;
    }

    const float4* xb4 = (const float4*)(x + (size_t)b * TT * DD);
    const float4* n0 = xb4 + (size_t)sel[0] * 256;
    const float4* n1 = xb4 + (size_t)sel[1] * 256;
    const float4* n2 = xb4 + (size_t)sel[2] * 256;
    const float4* n3 = xb4 + (size_t)sel[3] * 256;
    float4* o4 = (float4*)out + (size_t)row * 256;

    #pragma unroll
    for (int j = 0; j < 8; j++) {
        int c = lane + j * 32;
        float4 A = n0[c], B = n1[c], C = n2[c], D = n3[c];
        float4 o;
        o.x = (A.x + B.x + C.x + D.x) * 0.25f;
        o.y = (A.y + B.y + C.y + D.y) * 0.25f;
        o.z = (A.z + B.z + C.z + D.z) * 0.25f;
        o.w = (A.w + B.w + C.w + D.w) * 0.25f;
        o4[c] = o;
    }
}

// ---------------------------------------------------------------------------
extern "C" void kernel_launch(void* const* d_in, const int* in_sizes, int n_in,
                              void* d_out, int out_size)
{
    const float* x  = (const float*)d_in[0];
    const float* Wq = (const float*)d_in[1];
    const float* bq = (const float*)d_in[2];
    const float* Wk = (const float*)d_in[3];
    const float* bk = (const float*)d_in[4];
    float* out = (float*)d_out;

    proj_kernel<<<512, 256>>>(x, Wq, Wk);
    reduce_kernel<<<128, 256>>>(bq, bk);
    sim_kernel<<<512, 256>>>();
    gather_kernel<<<1024, 256>>>(x, out);
}